// round 1
// baseline (speedup 1.0000x reference)
#include <cuda_runtime.h>

// Problem constants (fixed by the dataset)
#define NN 50000      // nodes
#define NE 800000     // edges
#define DVF 128       // node feature dim
#define DEF 64        // edge feature dim
#define DHH 64        // head dim
#define D3 192        // 3*DH
#define EPS 1e-5f
#define SCALE 0.07216878364870322f   // 1/sqrt(192)

// ---------------- scratch (device globals: the sanctioned no-alloc workaround) ----
__device__ float g_Q  [NN * DHH];
__device__ float g_K  [NN * DHH];
__device__ float g_V  [NN * DHH];
__device__ float g_Vu1[NN * D3];     // V @ Wu[0:64,:]
__device__ float g_Vu2[NN * D3];     // V @ Wu[64:128,:]
__device__ int   g_i1 [NE];
__device__ int   g_i2 [NE];
__device__ int   g_is64;

// ---------------- idx dtype detection (int64 vs int32, deterministic) ------------
__global__ void k_detect(const void* idx1) {
    const long long* p = (const long long*)idx1;
    bool ok = true;
    #pragma unroll
    for (int i = 0; i < 8; i++) {
        long long v = p[i];
        if (v < 0 || v >= NN) ok = false;
    }
    g_is64 = ok ? 1 : 0;
}

__global__ void k_cvt(const void* idx1, const void* idx2) {
    int is64 = g_is64;
    int stride = gridDim.x * blockDim.x;
    for (int i = blockIdx.x * blockDim.x + threadIdx.x; i < NE; i += stride) {
        if (is64) {
            g_i1[i] = (int)((const long long*)idx1)[i];
            g_i2[i] = (int)((const long long*)idx2)[i];
        } else {
            g_i1[i] = ((const int*)idx1)[i];
            g_i2[i] = ((const int*)idx2)[i];
        }
    }
}

// ---------------- zero the output (it is poisoned to 0xAA) -----------------------
__global__ void k_zero(float4* out, int n4) {
    int stride = gridDim.x * blockDim.x;
    for (int i = blockIdx.x * blockDim.x + threadIdx.x; i < n4; i += stride)
        out[i] = make_float4(0.f, 0.f, 0.f, 0.f);
}

// ---------------- node prep 1: Q,K,V = node_fea @ [WQ|WK|WV] + b -----------------
// 148 persistent blocks, 256 threads, 32 nodes/tile.
// smem: W[128][192] + b[192] + nf[32][132(pad)]
#define QKV_SMEM_FLOATS (128*192 + 192 + 32*132)
__global__ void __launch_bounds__(256, 1)
k_node_qkv(const float* __restrict__ nf,
           const float* __restrict__ WQ, const float* __restrict__ bQ,
           const float* __restrict__ WK, const float* __restrict__ bK,
           const float* __restrict__ WV, const float* __restrict__ bV) {
    extern __shared__ float sm[];
    float* sW  = sm;                  // [128][192]
    float* sB  = sW + 128 * 192;      // [192]
    float* sNF = sB + 192;            // [32][132]
    int t = threadIdx.x;

    for (int i = t; i < 128 * 64; i += 256) {
        int k = i >> 6, j = i & 63;
        sW[k * 192 + j]        = WQ[i];
        sW[k * 192 + 64 + j]   = WK[i];
        sW[k * 192 + 128 + j]  = WV[i];
    }
    for (int i = t; i < 192; i += 256)
        sB[i] = (i < 64) ? bQ[i] : (i < 128) ? bK[i - 64] : bV[i - 128];
    __syncthreads();

    int warp = t >> 5, lane = t & 31;
    const int TILES = (NN + 31) / 32;
    for (int tile = blockIdx.x; tile < TILES; tile += gridDim.x) {
        int n0 = tile * 32;
        __syncthreads();  // protect sNF from previous iteration's readers
        #pragma unroll
        for (int r = 0; r < 4; r++) {
            int f4 = r * 256 + t;            // float4 index: row = f4/32, c4 = f4%32
            int row = f4 >> 5, c4 = f4 & 31;
            int n = n0 + row;
            float4 v = make_float4(0.f, 0.f, 0.f, 0.f);
            if (n < NN) v = ((const float4*)(nf + (size_t)n * DVF))[c4];
            *((float4*)(sNF + row * 132 + c4 * 4)) = v;
        }
        __syncthreads();

        float acc[4][6];
        #pragma unroll
        for (int i = 0; i < 4; i++)
            #pragma unroll
            for (int j = 0; j < 6; j++) acc[i][j] = 0.f;

        #pragma unroll 4
        for (int k = 0; k < 128; k++) {
            float a0 = sNF[(warp * 4 + 0) * 132 + k];
            float a1 = sNF[(warp * 4 + 1) * 132 + k];
            float a2 = sNF[(warp * 4 + 2) * 132 + k];
            float a3 = sNF[(warp * 4 + 3) * 132 + k];
            #pragma unroll
            for (int j = 0; j < 6; j++) {
                float w = sW[k * 192 + lane + 32 * j];
                acc[0][j] += a0 * w;
                acc[1][j] += a1 * w;
                acc[2][j] += a2 * w;
                acc[3][j] += a3 * w;
            }
        }
        #pragma unroll
        for (int i = 0; i < 4; i++) {
            int n = n0 + warp * 4 + i;
            if (n < NN) {
                #pragma unroll
                for (int j = 0; j < 6; j++) {
                    int c = lane + 32 * j;
                    float v = acc[i][j] + sB[c];
                    if (j < 2)      g_Q[n * DHH + c]        = v;
                    else if (j < 4) g_K[n * DHH + (c - 64)] = v;
                    else            g_V[n * DHH + (c - 128)] = v;
                }
            }
        }
    }
}

// ---------------- node prep 2: Vu1 = V@Wu_top, Vu2 = V@Wu_mid --------------------
#define VU_SMEM_FLOATS (128*192 + 32*68)
__global__ void __launch_bounds__(256, 1)
k_node_vu(const float* __restrict__ Wu) {
    extern __shared__ float sm[];
    float* sW = sm;                  // Wu rows 0..127, [128][192]
    float* sV = sW + 128 * 192;      // [32][68]
    int t = threadIdx.x;

    for (int i = t; i < 128 * 192; i += 256) sW[i] = Wu[i];
    __syncthreads();

    int warp = t >> 5, lane = t & 31;
    const int TILES = (NN + 31) / 32;
    for (int tile = blockIdx.x; tile < TILES; tile += gridDim.x) {
        int n0 = tile * 32;
        __syncthreads();
        #pragma unroll
        for (int r = 0; r < 2; r++) {
            int f4 = r * 256 + t;           // row = f4/16, c4 = f4%16
            int row = f4 >> 4, c4 = f4 & 15;
            int n = n0 + row;
            float4 v = make_float4(0.f, 0.f, 0.f, 0.f);
            if (n < NN) v = ((const float4*)(g_V + (size_t)n * DHH))[c4];
            *((float4*)(sV + row * 68 + c4 * 4)) = v;
        }
        __syncthreads();

        float acc[4][12];
        #pragma unroll
        for (int i = 0; i < 4; i++)
            #pragma unroll
            for (int j = 0; j < 12; j++) acc[i][j] = 0.f;

        #pragma unroll 2
        for (int k = 0; k < 64; k++) {
            float a0 = sV[(warp * 4 + 0) * 68 + k];
            float a1 = sV[(warp * 4 + 1) * 68 + k];
            float a2 = sV[(warp * 4 + 2) * 68 + k];
            float a3 = sV[(warp * 4 + 3) * 68 + k];
            #pragma unroll
            for (int j = 0; j < 6; j++) {
                float w1 = sW[k * 192 + lane + 32 * j];          // Wu rows 0..63
                float w2 = sW[(64 + k) * 192 + lane + 32 * j];   // Wu rows 64..127
                acc[0][j] += a0 * w1;  acc[0][6 + j] += a0 * w2;
                acc[1][j] += a1 * w1;  acc[1][6 + j] += a1 * w2;
                acc[2][j] += a2 * w1;  acc[2][6 + j] += a2 * w2;
                acc[3][j] += a3 * w1;  acc[3][6 + j] += a3 * w2;
            }
        }
        #pragma unroll
        for (int i = 0; i < 4; i++) {
            int n = n0 + warp * 4 + i;
            if (n < NN) {
                #pragma unroll
                for (int j = 0; j < 6; j++) {
                    g_Vu1[(size_t)n * D3 + lane + 32 * j] = acc[i][j];
                    g_Vu2[(size_t)n * D3 + lane + 32 * j] = acc[i][6 + j];
                }
            }
        }
    }
}

// ---------------- fused edge kernel ---------------------------------------------
// 148 persistent blocks x 256 threads. Each WARP independently processes quads of
// 4 edges (8 lanes/edge). All edge-side weights resident in smem; no block
// barriers inside the mainloop.
#define EDGE_SMEM_FLOATS (4096 + 12288 + 24576 + 1024 + 8*4*72 + 8*4*72 + 8*4*200)
__global__ void __launch_bounds__(256, 1)
k_edge(const float* __restrict__ edge_fea,
       const float* __restrict__ WE, const float* __restrict__ bE,
       const float* __restrict__ Wu, const float* __restrict__ bu,
       const float* __restrict__ Wm, const float* __restrict__ bm,
       const float* __restrict__ g1, const float* __restrict__ b1,
       const float* __restrict__ g2, const float* __restrict__ b2,
       float* __restrict__ out) {
    extern __shared__ float sm[];
    float* sWE  = sm;                   // [64][64]
    float* sWub = sWE + 4096;           // Wu rows 128..191: [64][192]
    float* sWm  = sWub + 12288;         // [192][128]
    float* sbE  = sWm + 24576;          // 64
    float* sbu  = sbE + 64;             // 192
    float* sbm  = sbu + 192;            // 128
    float* sg1  = sbm + 128;            // 192
    float* sb1  = sg1 + 192;            // 192
    float* sg2  = sb1 + 192;            // 128
    float* sb2  = sg2 + 128;            // 128
    float* sEF  = sb2 + 128;            // [8 warps][4][72]
    float* sEP  = sEF + 8 * 4 * 72;     // [8 warps][4][72]
    float* sM   = sEP + 8 * 4 * 72;     // [8 warps][4][200]

    int t = threadIdx.x;
    for (int i = t; i < 4096;  i += 256) sWE[i]  = WE[i];
    for (int i = t; i < 12288; i += 256) sWub[i] = Wu[128 * 192 + i];
    for (int i = t; i < 24576; i += 256) sWm[i]  = Wm[i];
    for (int i = t; i < 64;    i += 256) sbE[i]  = bE[i];
    for (int i = t; i < 192;   i += 256) { sbu[i] = bu[i]; sg1[i] = g1[i]; sb1[i] = b1[i]; }
    for (int i = t; i < 128;   i += 256) { sbm[i] = bm[i]; sg2[i] = g2[i]; sb2[i] = b2[i]; }
    __syncthreads();

    int warp = t >> 5, lane = t & 31;
    int el = lane >> 3;    // edge-in-quad 0..3
    int cs = lane & 7;     // column-slice 0..7
    float* myEF = sEF + warp * (4 * 72);
    float* myEP = sEP + warp * (4 * 72);
    float* myM  = sM  + warp * (4 * 200);

    int gw = blockIdx.x * 8 + warp;
    const int NQ = NE / 4;
    for (int qd = gw; qd < NQ; qd += gridDim.x * 8) {
        int e  = qd * 4 + el;
        int i1 = g_i1[e];
        int i2 = g_i2[e];

        // ---- stage edge_fea quad (4 rows x 64) : coalesced, warp-private -------
        {
            const float4* src = (const float4*)(edge_fea + (size_t)qd * 4 * DEF);
            float4 v0 = src[lane * 2];
            float4 v1 = src[lane * 2 + 1];
            *((float4*)(myEF + el * 72 + cs * 8))     = v0;   // row=lane/8, col=cs*8
            *((float4*)(myEF + el * 72 + cs * 8 + 4)) = v1;
        }
        __syncwarp();

        // ---- Ep[cs*8 .. cs*8+8) = edge_fea @ WE + bE ---------------------------
        float ep[8];
        #pragma unroll
        for (int j = 0; j < 8; j++) ep[j] = sbE[cs * 8 + j];
        #pragma unroll 4
        for (int k = 0; k < 64; k++) {
            float a = myEF[el * 72 + k];
            const float4* w4 = (const float4*)(sWE + k * 64 + cs * 8);
            float4 wa = w4[0], wb = w4[1];
            ep[0] += a * wa.x; ep[1] += a * wa.y; ep[2] += a * wa.z; ep[3] += a * wa.w;
            ep[4] += a * wb.x; ep[5] += a * wb.y; ep[6] += a * wb.z; ep[7] += a * wb.w;
        }
        *((float4*)(myEP + el * 72 + cs * 8))     = make_float4(ep[0], ep[1], ep[2], ep[3]);
        *((float4*)(myEP + el * 72 + cs * 8 + 4)) = make_float4(ep[4], ep[5], ep[6], ep[7]);

        // ---- aij = [Qi*K1, Qi*K2, Qi*Ep] * SCALE  (24 values per lane) ---------
        float a[24];
        {
            const float4* qp  = (const float4*)(g_Q + (size_t)i1 * DHH + cs * 8);
            const float4* k1p = (const float4*)(g_K + (size_t)i1 * DHH + cs * 8);
            const float4* k2p = (const float4*)(g_K + (size_t)i2 * DHH + cs * 8);
            float4 q0 = qp[0],  q1 = qp[1];
            float4 ka0 = k1p[0], ka1 = k1p[1];
            float4 kb0 = k2p[0], kb1 = k2p[1];
            a[0]  = q0.x * ka0.x * SCALE; a[1]  = q0.y * ka0.y * SCALE;
            a[2]  = q0.z * ka0.z * SCALE; a[3]  = q0.w * ka0.w * SCALE;
            a[4]  = q1.x * ka1.x * SCALE; a[5]  = q1.y * ka1.y * SCALE;
            a[6]  = q1.z * ka1.z * SCALE; a[7]  = q1.w * ka1.w * SCALE;
            a[8]  = q0.x * kb0.x * SCALE; a[9]  = q0.y * kb0.y * SCALE;
            a[10] = q0.z * kb0.z * SCALE; a[11] = q0.w * kb0.w * SCALE;
            a[12] = q1.x * kb1.x * SCALE; a[13] = q1.y * kb1.y * SCALE;
            a[14] = q1.z * kb1.z * SCALE; a[15] = q1.w * kb1.w * SCALE;
            a[16] = q0.x * ep[0] * SCALE; a[17] = q0.y * ep[1] * SCALE;
            a[18] = q0.z * ep[2] * SCALE; a[19] = q0.w * ep[3] * SCALE;
            a[20] = q1.x * ep[4] * SCALE; a[21] = q1.y * ep[5] * SCALE;
            a[22] = q1.z * ep[6] * SCALE; a[23] = q1.w * ep[7] * SCALE;
        }
        // LN1 stats over 192 (8 lanes per edge)
        float s = 0.f, ss = 0.f;
        #pragma unroll
        for (int j = 0; j < 24; j++) { s += a[j]; ss += a[j] * a[j]; }
        #pragma unroll
        for (int off = 1; off < 8; off <<= 1) {
            s  += __shfl_xor_sync(0xffffffffu, s,  off);
            ss += __shfl_xor_sync(0xffffffffu, ss, off);
        }
        float mean = s * (1.f / 192.f);
        float var  = ss * (1.f / 192.f) - mean * mean;
        float rstd = rsqrtf(var + EPS);
        // sigmoid(LN1(a)) -> smem
        #pragma unroll
        for (int p = 0; p < 3; p++) {
            float v[8];
            #pragma unroll
            for (int j = 0; j < 8; j++) {
                int c = p * 64 + cs * 8 + j;
                float x = (a[p * 8 + j] - mean) * rstd * sg1[c] + sb1[c];
                v[j] = 1.f / (1.f + __expf(-x));
            }
            *((float4*)(myM + el * 200 + p * 64 + cs * 8))     = make_float4(v[0], v[1], v[2], v[3]);
            *((float4*)(myM + el * 200 + p * 64 + cs * 8 + 4)) = make_float4(v[4], v[5], v[6], v[7]);
        }
        __syncwarp();

        // ---- u = Vu1[i1] + Vu2[i2] + Ep@Wu_bot + bu ; m = sig * u --------------
        float acc[24];
        {
            const float4* v1p = (const float4*)(g_Vu1 + (size_t)i1 * D3 + cs * 24);
            const float4* v2p = (const float4*)(g_Vu2 + (size_t)i2 * D3 + cs * 24);
            #pragma unroll
            for (int j4 = 0; j4 < 6; j4++) {
                float4 x = v1p[j4], y = v2p[j4];
                acc[j4 * 4 + 0] = x.x + y.x + sbu[cs * 24 + j4 * 4 + 0];
                acc[j4 * 4 + 1] = x.y + y.y + sbu[cs * 24 + j4 * 4 + 1];
                acc[j4 * 4 + 2] = x.z + y.z + sbu[cs * 24 + j4 * 4 + 2];
                acc[j4 * 4 + 3] = x.w + y.w + sbu[cs * 24 + j4 * 4 + 3];
            }
        }
        #pragma unroll 2
        for (int k = 0; k < 64; k++) {
            float epv = myEP[el * 72 + k];
            const float4* w4 = (const float4*)(sWub + k * 192 + cs * 24);
            #pragma unroll
            for (int j4 = 0; j4 < 6; j4++) {
                float4 w = w4[j4];
                acc[j4 * 4 + 0] += epv * w.x;
                acc[j4 * 4 + 1] += epv * w.y;
                acc[j4 * 4 + 2] += epv * w.z;
                acc[j4 * 4 + 3] += epv * w.w;
            }
        }
        #pragma unroll
        for (int j4 = 0; j4 < 6; j4++) {
            float4 sg = *((const float4*)(myM + el * 200 + cs * 24 + j4 * 4));
            float4 mv;
            mv.x = sg.x * acc[j4 * 4 + 0];
            mv.y = sg.y * acc[j4 * 4 + 1];
            mv.z = sg.z * acc[j4 * 4 + 2];
            mv.w = sg.w * acc[j4 * 4 + 3];
            *((float4*)(myM + el * 200 + cs * 24 + j4 * 4)) = mv;
        }
        __syncwarp();

        // ---- msg = LN2(m @ Wm + bm); atomic scatter to out[i1] -----------------
        float o[16];
        #pragma unroll
        for (int j = 0; j < 16; j++) o[j] = sbm[cs * 16 + j];
        #pragma unroll 2
        for (int c = 0; c < 192; c++) {
            float mv = myM[el * 200 + c];
            const float4* w4 = (const float4*)(sWm + c * 128 + cs * 16);
            #pragma unroll
            for (int j4 = 0; j4 < 4; j4++) {
                float4 w = w4[j4];
                o[j4 * 4 + 0] += mv * w.x;
                o[j4 * 4 + 1] += mv * w.y;
                o[j4 * 4 + 2] += mv * w.z;
                o[j4 * 4 + 3] += mv * w.w;
            }
        }
        float s2 = 0.f, ss2 = 0.f;
        #pragma unroll
        for (int j = 0; j < 16; j++) { s2 += o[j]; ss2 += o[j] * o[j]; }
        #pragma unroll
        for (int off = 1; off < 8; off <<= 1) {
            s2  += __shfl_xor_sync(0xffffffffu, s2,  off);
            ss2 += __shfl_xor_sync(0xffffffffu, ss2, off);
        }
        float mean2 = s2 * (1.f / 128.f);
        float var2  = ss2 * (1.f / 128.f) - mean2 * mean2;
        float rstd2 = rsqrtf(var2 + EPS);
        float* op = out + (size_t)i1 * DVF + cs * 16;
        #pragma unroll
        for (int j = 0; j < 16; j++) {
            int d = cs * 16 + j;
            float val = (o[j] - mean2) * rstd2 * sg2[d] + sb2[d];
            atomicAdd(op + j, val);
        }
        __syncwarp();   // all lanes done with myEF/myEP/myM before next quad
    }
}

// ---------------- launch ---------------------------------------------------------
extern "C" void kernel_launch(void* const* d_in, const int* in_sizes, int n_in,
                              void* d_out, int out_size) {
    const float* node_fea = (const float*)d_in[0];
    const void*  idx1     = d_in[1];
    const void*  idx2     = d_in[2];
    const float* edge_fea = (const float*)d_in[3];
    const float* WQ = (const float*)d_in[4];  const float* bQ = (const float*)d_in[5];
    const float* WK = (const float*)d_in[6];  const float* bK = (const float*)d_in[7];
    const float* WV = (const float*)d_in[8];  const float* bV = (const float*)d_in[9];
    const float* WE = (const float*)d_in[10]; const float* bE = (const float*)d_in[11];
    const float* Wu = (const float*)d_in[12]; const float* bu = (const float*)d_in[13];
    const float* Wm = (const float*)d_in[14]; const float* bm = (const float*)d_in[15];
    const float* g1 = (const float*)d_in[16]; const float* b1 = (const float*)d_in[17];
    const float* g2 = (const float*)d_in[18]; const float* b2 = (const float*)d_in[19];
    float* out = (float*)d_out;

    // Opt-in to >48KB dynamic smem (idempotent; not a stream op, capture-safe)
    cudaFuncSetAttribute(k_node_qkv, cudaFuncAttributeMaxDynamicSharedMemorySize,
                         QKV_SMEM_FLOATS * 4);
    cudaFuncSetAttribute(k_node_vu, cudaFuncAttributeMaxDynamicSharedMemorySize,
                         VU_SMEM_FLOATS * 4);
    cudaFuncSetAttribute(k_edge, cudaFuncAttributeMaxDynamicSharedMemorySize,
                         EDGE_SMEM_FLOATS * 4);

    k_detect<<<1, 1>>>(idx1);
    k_cvt<<<400, 256>>>(idx1, idx2);
    k_zero<<<1600, 256>>>((float4*)out, NN * DVF / 4);
    k_node_qkv<<<148, 256, QKV_SMEM_FLOATS * 4>>>(node_fea, WQ, bQ, WK, bK, WV, bV);
    k_node_vu<<<148, 256, VU_SMEM_FLOATS * 4>>>(Wu);
    k_edge<<<148, 256, EDGE_SMEM_FLOATS * 4>>>(edge_fea, WE, bE, Wu, bu, Wm, bm,
                                               g1, b1, g2, b2, out);
}

// round 3
// speedup vs baseline: 5.3239x; 5.3239x over previous
#include <cuda_runtime.h>

#define NN 50000
#define NE 800000
#define DVF 128
#define DEF 64
#define DHH 64
#define D3 192
#define EPS 1e-5f
#define SCALE 0.07216878364870322f   // 1/sqrt(192)
#define FULLMASK 0xffffffffu

// ---------------- scratch ---------------------------------------------------------
__device__ float g_Q  [NN * DHH];
__device__ float g_K  [NN * DHH];
__device__ float g_V  [NN * DHH];
__device__ float g_Vu1[NN * D3];
__device__ float g_Vu2[NN * D3];
__device__ __align__(16) int g_i1[NE];
__device__ __align__(16) int g_i2[NE];
__device__ int   g_is64;

// ---------------- idx dtype detect + convert --------------------------------------
__global__ void k_detect(const void* idx1) {
    const long long* p = (const long long*)idx1;
    bool ok = true;
    #pragma unroll
    for (int i = 0; i < 8; i++) {
        long long v = p[i];
        if (v < 0 || v >= NN) ok = false;
    }
    g_is64 = ok ? 1 : 0;
}

__global__ void k_cvt(const void* idx1, const void* idx2) {
    int is64 = g_is64;
    int stride = gridDim.x * blockDim.x;
    for (int i = blockIdx.x * blockDim.x + threadIdx.x; i < NE; i += stride) {
        if (is64) {
            g_i1[i] = (int)((const long long*)idx1)[i];
            g_i2[i] = (int)((const long long*)idx2)[i];
        } else {
            g_i1[i] = ((const int*)idx1)[i];
            g_i2[i] = ((const int*)idx2)[i];
        }
    }
}

__global__ void k_zero(float4* out, int n4) {
    int stride = gridDim.x * blockDim.x;
    for (int i = blockIdx.x * blockDim.x + threadIdx.x; i < n4; i += stride)
        out[i] = make_float4(0.f, 0.f, 0.f, 0.f);
}

// ---------------- node prep 1: Q,K,V ----------------------------------------------
#define QKV_SMEM_FLOATS (128*192 + 192 + 32*132)
__global__ void __launch_bounds__(256, 1)
k_node_qkv(const float* __restrict__ nf,
           const float* __restrict__ WQ, const float* __restrict__ bQ,
           const float* __restrict__ WK, const float* __restrict__ bK,
           const float* __restrict__ WV, const float* __restrict__ bV) {
    extern __shared__ float sm[];
    float* sW  = sm;
    float* sB  = sW + 128 * 192;
    float* sNF = sB + 192;
    int t = threadIdx.x;

    for (int i = t; i < 128 * 64; i += 256) {
        int k = i >> 6, j = i & 63;
        sW[k * 192 + j]       = WQ[i];
        sW[k * 192 + 64 + j]  = WK[i];
        sW[k * 192 + 128 + j] = WV[i];
    }
    for (int i = t; i < 192; i += 256)
        sB[i] = (i < 64) ? bQ[i] : (i < 128) ? bK[i - 64] : bV[i - 128];
    __syncthreads();

    int warp = t >> 5, lane = t & 31;
    const int TILES = (NN + 31) / 32;
    for (int tile = blockIdx.x; tile < TILES; tile += gridDim.x) {
        int n0 = tile * 32;
        __syncthreads();
        #pragma unroll
        for (int r = 0; r < 4; r++) {
            int f4 = r * 256 + t;
            int row = f4 >> 5, c4 = f4 & 31;
            int n = n0 + row;
            float4 v = make_float4(0.f, 0.f, 0.f, 0.f);
            if (n < NN) v = ((const float4*)(nf + (size_t)n * DVF))[c4];
            *((float4*)(sNF + row * 132 + c4 * 4)) = v;
        }
        __syncthreads();

        float acc[4][6];
        #pragma unroll
        for (int i = 0; i < 4; i++)
            #pragma unroll
            for (int j = 0; j < 6; j++) acc[i][j] = 0.f;

        #pragma unroll 4
        for (int k = 0; k < 128; k++) {
            float a0 = sNF[(warp * 4 + 0) * 132 + k];
            float a1 = sNF[(warp * 4 + 1) * 132 + k];
            float a2 = sNF[(warp * 4 + 2) * 132 + k];
            float a3 = sNF[(warp * 4 + 3) * 132 + k];
            #pragma unroll
            for (int j = 0; j < 6; j++) {
                float w = sW[k * 192 + lane + 32 * j];
                acc[0][j] += a0 * w;
                acc[1][j] += a1 * w;
                acc[2][j] += a2 * w;
                acc[3][j] += a3 * w;
            }
        }
        #pragma unroll
        for (int i = 0; i < 4; i++) {
            int n = n0 + warp * 4 + i;
            if (n < NN) {
                #pragma unroll
                for (int j = 0; j < 6; j++) {
                    int c = lane + 32 * j;
                    float v = acc[i][j] + sB[c];
                    if (j < 2)      g_Q[n * DHH + c]         = v;
                    else if (j < 4) g_K[n * DHH + (c - 64)]  = v;
                    else            g_V[n * DHH + (c - 128)] = v;
                }
            }
        }
    }
}

// ---------------- node prep 2: Vu1,Vu2 --------------------------------------------
#define VU_SMEM_FLOATS (128*192 + 32*68)
__global__ void __launch_bounds__(256, 1)
k_node_vu(const float* __restrict__ Wu) {
    extern __shared__ float sm[];
    float* sW = sm;
    float* sV = sW + 128 * 192;
    int t = threadIdx.x;

    for (int i = t; i < 128 * 192; i += 256) sW[i] = Wu[i];
    __syncthreads();

    int warp = t >> 5, lane = t & 31;
    const int TILES = (NN + 31) / 32;
    for (int tile = blockIdx.x; tile < TILES; tile += gridDim.x) {
        int n0 = tile * 32;
        __syncthreads();
        #pragma unroll
        for (int r = 0; r < 2; r++) {
            int f4 = r * 256 + t;
            int row = f4 >> 4, c4 = f4 & 15;
            int n = n0 + row;
            float4 v = make_float4(0.f, 0.f, 0.f, 0.f);
            if (n < NN) v = ((const float4*)(g_V + (size_t)n * DHH))[c4];
            *((float4*)(sV + row * 68 + c4 * 4)) = v;
        }
        __syncthreads();

        float acc[4][12];
        #pragma unroll
        for (int i = 0; i < 4; i++)
            #pragma unroll
            for (int j = 0; j < 12; j++) acc[i][j] = 0.f;

        #pragma unroll 2
        for (int k = 0; k < 64; k++) {
            float a0 = sV[(warp * 4 + 0) * 68 + k];
            float a1 = sV[(warp * 4 + 1) * 68 + k];
            float a2 = sV[(warp * 4 + 2) * 68 + k];
            float a3 = sV[(warp * 4 + 3) * 68 + k];
            #pragma unroll
            for (int j = 0; j < 6; j++) {
                float w1 = sW[k * 192 + lane + 32 * j];
                float w2 = sW[(64 + k) * 192 + lane + 32 * j];
                acc[0][j] += a0 * w1;  acc[0][6 + j] += a0 * w2;
                acc[1][j] += a1 * w1;  acc[1][6 + j] += a1 * w2;
                acc[2][j] += a2 * w1;  acc[2][6 + j] += a2 * w2;
                acc[3][j] += a3 * w1;  acc[3][6 + j] += a3 * w2;
            }
        }
        #pragma unroll
        for (int i = 0; i < 4; i++) {
            int n = n0 + warp * 4 + i;
            if (n < NN) {
                #pragma unroll
                for (int j = 0; j < 6; j++) {
                    g_Vu1[(size_t)n * D3 + lane + 32 * j] = acc[i][j];
                    g_Vu2[(size_t)n * D3 + lane + 32 * j] = acc[i][6 + j];
                }
            }
        }
    }
}

// ---------------- fused edge kernel (lane = output column; conflict-free) ---------
// 148 blocks x 512 threads (16 warps/SM). Each warp: quads of 4 edges.
// Lane L owns output columns {L, L+32, ...}. All weight LDS stride-1.
#define EDGE_SMEM_FLOATS (4096 + 12288 + 24576 + 1024 + 16*768)

__device__ __forceinline__ float4 shfl4(float4 v, int src) {
    float4 r;
    r.x = __shfl_sync(FULLMASK, v.x, src);
    r.y = __shfl_sync(FULLMASK, v.y, src);
    r.z = __shfl_sync(FULLMASK, v.z, src);
    r.w = __shfl_sync(FULLMASK, v.w, src);
    return r;
}

__global__ void __launch_bounds__(512, 1)
k_edge(const float* __restrict__ edge_fea,
       const float* __restrict__ WE, const float* __restrict__ bE,
       const float* __restrict__ Wu, const float* __restrict__ bu,
       const float* __restrict__ Wm, const float* __restrict__ bm,
       const float* __restrict__ g1, const float* __restrict__ b1,
       const float* __restrict__ g2, const float* __restrict__ b2,
       float* __restrict__ out) {
    extern __shared__ float sm[];
    float* sWE  = sm;                   // [64][64]
    float* sWub = sWE + 4096;           // Wu rows 128..191 [64][192]
    float* sWm  = sWub + 12288;         // [192][128]
    float* sbE  = sWm + 24576;          // 64
    float* sbu  = sbE + 64;             // 192
    float* sbm  = sbu + 192;            // 128
    float* sg1  = sbm + 128;            // 192
    float* sb1  = sg1 + 192;            // 192
    float* sg2  = sb1 + 192;            // 128
    float* sb2  = sg2 + 128;            // 128
    float* sM   = sb2 + 128;            // [16 warps][4][192]

    int t = threadIdx.x;
    for (int i = t; i < 4096;  i += 512) sWE[i]  = WE[i];
    for (int i = t; i < 12288; i += 512) sWub[i] = Wu[128 * 192 + i];
    for (int i = t; i < 24576; i += 512) sWm[i]  = Wm[i];
    if (t < 64)  sbE[t] = bE[t];
    if (t < 192) { sbu[t] = bu[t]; sg1[t] = g1[t]; sb1[t] = b1[t]; }
    if (t < 128) { sbm[t] = bm[t]; sg2[t] = g2[t]; sb2[t] = b2[t]; }
    __syncthreads();

    int warp = t >> 5, lane = t & 31;
    float* sMw = sM + warp * 768;

    int gw = blockIdx.x * 16 + warp;
    const int NQ = NE / 4;
    for (int qd = gw; qd < NQ; qd += gridDim.x * 16) {
        // ---- indices (vector load, 16B-aligned) + early gathers -----------------
        int4 i1q = *(const int4*)(g_i1 + qd * 4);
        int4 i2q = *(const int4*)(g_i2 + qd * 4);
        int i1v[4] = { i1q.x, i1q.y, i1q.z, i1q.w };
        int i2v[4] = { i2q.x, i2q.y, i2q.z, i2q.w };

        float u[4][6];                       // u = Vu1[i1] + Vu2[i2] + bu
        #pragma unroll
        for (int el = 0; el < 4; el++) {
            const float* p1 = g_Vu1 + i1v[el] * D3;
            const float* p2 = g_Vu2 + i2v[el] * D3;
            #pragma unroll
            for (int j = 0; j < 6; j++)
                u[el][j] = p1[j * 32 + lane] + p2[j * 32 + lane] + sbu[j * 32 + lane];
        }
        // Q/K gathers; fold into aij immediately (frees k registers)
        float a[4][6];
        float qr[4][2];
        #pragma unroll
        for (int el = 0; el < 4; el++) {
            const float* pq  = g_Q + i1v[el] * DHH;
            const float* pk1 = g_K + i1v[el] * DHH;
            const float* pk2 = g_K + i2v[el] * DHH;
            #pragma unroll
            for (int jj = 0; jj < 2; jj++) {
                qr[el][jj] = pq[jj * 32 + lane];
                a[el][0 + jj] = qr[el][jj] * pk1[jj * 32 + lane] * SCALE;
                a[el][2 + jj] = qr[el][jj] * pk2[jj * 32 + lane] * SCALE;
            }
        }
        // edge_fea quad -> registers (lane L: float4 #L and #L+32 of 64)
        const float4* efsrc = (const float4*)(edge_fea + (size_t)qd * 4 * DEF);
        float4 efA = efsrc[lane];
        float4 efB = efsrc[lane + 32];

        // ---- Ep = EF @ WE + bE (lane-column; EF broadcast via shuffle) ----------
        float ep[4][2];
        #pragma unroll
        for (int el = 0; el < 4; el++) { ep[el][0] = sbE[lane]; ep[el][1] = sbE[32 + lane]; }
        for (int k4 = 0; k4 < 16; k4++) {
            float tt[4][4];
            {
                float4 s0 = shfl4(efA, k4);
                float4 s1 = shfl4(efA, 16 + k4);
                float4 s2 = shfl4(efB, k4);
                float4 s3 = shfl4(efB, 16 + k4);
                tt[0][0]=s0.x; tt[0][1]=s0.y; tt[0][2]=s0.z; tt[0][3]=s0.w;
                tt[1][0]=s1.x; tt[1][1]=s1.y; tt[1][2]=s1.z; tt[1][3]=s1.w;
                tt[2][0]=s2.x; tt[2][1]=s2.y; tt[2][2]=s2.z; tt[2][3]=s2.w;
                tt[3][0]=s3.x; tt[3][1]=s3.y; tt[3][2]=s3.z; tt[3][3]=s3.w;
            }
            #pragma unroll
            for (int kk = 0; kk < 4; kk++) {
                int k = k4 * 4 + kk;
                float w0 = sWE[k * 64 + lane];
                float w1 = sWE[k * 64 + 32 + lane];
                #pragma unroll
                for (int el = 0; el < 4; el++) {
                    ep[el][0] += tt[el][kk] * w0;
                    ep[el][1] += tt[el][kk] * w1;
                }
            }
        }

        // ---- finish aij + LN1 stats --------------------------------------------
        #pragma unroll
        for (int el = 0; el < 4; el++)
            #pragma unroll
            for (int jj = 0; jj < 2; jj++)
                a[el][4 + jj] = qr[el][jj] * ep[el][jj] * SCALE;
        float s[4], ss[4];
        #pragma unroll
        for (int el = 0; el < 4; el++) {
            s[el] = 0.f; ss[el] = 0.f;
            #pragma unroll
            for (int j = 0; j < 6; j++) { s[el] += a[el][j]; ss[el] += a[el][j] * a[el][j]; }
        }
        #pragma unroll
        for (int off = 1; off < 32; off <<= 1)
            #pragma unroll
            for (int el = 0; el < 4; el++) {
                s[el]  += __shfl_xor_sync(FULLMASK, s[el],  off);
                ss[el] += __shfl_xor_sync(FULLMASK, ss[el], off);
            }
        float mean[4], rstd[4];
        #pragma unroll
        for (int el = 0; el < 4; el++) {
            mean[el] = s[el] * (1.f / 192.f);
            float var = ss[el] * (1.f / 192.f) - mean[el] * mean[el];
            rstd[el] = rsqrtf(var + EPS);
        }

        // ---- u += Ep @ Wu_bot (Ep broadcast via shuffle) ------------------------
        #pragma unroll
        for (int half = 0; half < 2; half++)
            for (int k5 = 0; k5 < 32; k5++) {
                float e0 = __shfl_sync(FULLMASK, ep[0][half], k5);
                float e1 = __shfl_sync(FULLMASK, ep[1][half], k5);
                float e2 = __shfl_sync(FULLMASK, ep[2][half], k5);
                float e3 = __shfl_sync(FULLMASK, ep[3][half], k5);
                int k = half * 32 + k5;
                #pragma unroll
                for (int j = 0; j < 6; j++) {
                    float w = sWub[k * 192 + j * 32 + lane];
                    u[0][j] += e0 * w;
                    u[1][j] += e1 * w;
                    u[2][j] += e2 * w;
                    u[3][j] += e3 * w;
                }
            }

        // ---- m = sigmoid(LN1(a)) * u  -> smem -----------------------------------
        #pragma unroll
        for (int el = 0; el < 4; el++)
            #pragma unroll
            for (int j = 0; j < 6; j++) {
                int c = j * 32 + lane;
                float x = (a[el][j] - mean[el]) * rstd[el] * sg1[c] + sb1[c];
                float sg = 1.f / (1.f + __expf(-x));
                sMw[el * 192 + c] = sg * u[el][j];
            }
        __syncwarp();

        // ---- o = m @ Wm + bm  (m broadcast via smem float4) ---------------------
        float o[4][4];
        #pragma unroll
        for (int el = 0; el < 4; el++)
            #pragma unroll
            for (int j = 0; j < 4; j++) o[el][j] = sbm[j * 32 + lane];
        for (int c4 = 0; c4 < 48; c4++) {
            float4 m0 = ((const float4*)(sMw + 0 * 192))[c4];
            float4 m1 = ((const float4*)(sMw + 1 * 192))[c4];
            float4 m2 = ((const float4*)(sMw + 2 * 192))[c4];
            float4 m3 = ((const float4*)(sMw + 3 * 192))[c4];
            float tm[4][4];
            tm[0][0]=m0.x; tm[0][1]=m0.y; tm[0][2]=m0.z; tm[0][3]=m0.w;
            tm[1][0]=m1.x; tm[1][1]=m1.y; tm[1][2]=m1.z; tm[1][3]=m1.w;
            tm[2][0]=m2.x; tm[2][1]=m2.y; tm[2][2]=m2.z; tm[2][3]=m2.w;
            tm[3][0]=m3.x; tm[3][1]=m3.y; tm[3][2]=m3.z; tm[3][3]=m3.w;
            #pragma unroll
            for (int cc = 0; cc < 4; cc++) {
                int c = c4 * 4 + cc;
                #pragma unroll
                for (int j = 0; j < 4; j++) {
                    float w = sWm[c * 128 + j * 32 + lane];
                    o[0][j] += tm[0][cc] * w;
                    o[1][j] += tm[1][cc] * w;
                    o[2][j] += tm[2][cc] * w;
                    o[3][j] += tm[3][cc] * w;
                }
            }
        }

        // ---- LN2 + atomic scatter ----------------------------------------------
        float s2[4], ss2[4];
        #pragma unroll
        for (int el = 0; el < 4; el++) {
            s2[el] = 0.f; ss2[el] = 0.f;
            #pragma unroll
            for (int j = 0; j < 4; j++) { s2[el] += o[el][j]; ss2[el] += o[el][j] * o[el][j]; }
        }
        #pragma unroll
        for (int off = 1; off < 32; off <<= 1)
            #pragma unroll
            for (int el = 0; el < 4; el++) {
                s2[el]  += __shfl_xor_sync(FULLMASK, s2[el],  off);
                ss2[el] += __shfl_xor_sync(FULLMASK, ss2[el], off);
            }
        #pragma unroll
        for (int el = 0; el < 4; el++) {
            float mean2 = s2[el] * (1.f / 128.f);
            float var2  = ss2[el] * (1.f / 128.f) - mean2 * mean2;
            float rstd2 = rsqrtf(var2 + EPS);
            float* op = out + (size_t)i1v[el] * DVF;
            #pragma unroll
            for (int j = 0; j < 4; j++) {
                int c = j * 32 + lane;
                float val = (o[el][j] - mean2) * rstd2 * sg2[c] + sb2[c];
                atomicAdd(op + c, val);
            }
        }
        __syncwarp();   // protect sMw before next iteration's writes
    }
}

// ---------------- launch ----------------------------------------------------------
extern "C" void kernel_launch(void* const* d_in, const int* in_sizes, int n_in,
                              void* d_out, int out_size) {
    const float* node_fea = (const float*)d_in[0];
    const void*  idx1     = d_in[1];
    const void*  idx2     = d_in[2];
    const float* edge_fea = (const float*)d_in[3];
    const float* WQ = (const float*)d_in[4];  const float* bQ = (const float*)d_in[5];
    const float* WK = (const float*)d_in[6];  const float* bK = (const float*)d_in[7];
    const float* WV = (const float*)d_in[8];  const float* bV = (const float*)d_in[9];
    const float* WE = (const float*)d_in[10]; const float* bE = (const float*)d_in[11];
    const float* Wu = (const float*)d_in[12]; const float* bu = (const float*)d_in[13];
    const float* Wm = (const float*)d_in[14]; const float* bm = (const float*)d_in[15];
    const float* g1 = (const float*)d_in[16]; const float* b1 = (const float*)d_in[17];
    const float* g2 = (const float*)d_in[18]; const float* b2 = (const float*)d_in[19];
    float* out = (float*)d_out;

    cudaFuncSetAttribute(k_node_qkv, cudaFuncAttributeMaxDynamicSharedMemorySize,
                         QKV_SMEM_FLOATS * 4);
    cudaFuncSetAttribute(k_node_vu, cudaFuncAttributeMaxDynamicSharedMemorySize,
                         VU_SMEM_FLOATS * 4);
    cudaFuncSetAttribute(k_edge, cudaFuncAttributeMaxDynamicSharedMemorySize,
                         EDGE_SMEM_FLOATS * 4);

    k_detect<<<1, 1>>>(idx1);
    k_cvt<<<400, 256>>>(idx1, idx2);
    k_zero<<<1600, 256>>>((float4*)out, NN * DVF / 4);
    k_node_qkv<<<148, 256, QKV_SMEM_FLOATS * 4>>>(node_fea, WQ, bQ, WK, bK, WV, bV);
    k_node_vu<<<148, 256, VU_SMEM_FLOATS * 4>>>(Wu);
    k_edge<<<148, 512, EDGE_SMEM_FLOATS * 4>>>(edge_fea, WE, bE, Wu, bu, Wm, bm,
                                               g1, b1, g2, b2, out);
}